// round 3
// baseline (speedup 1.0000x reference)
#include <cuda_runtime.h>
#include <cstdint>

// ResRNN, int16-quantized recurrent weights, f32x2 packed math.
//  K1 (GEMM fp32):  XI[t]  = inp_w @ x_t + inp_b
//  K2 (GEMM fp32):  A1[t]  = l1_w[:, :H] @ XI[t] + l1_b
//  SEQ (persistent, grid-sync), per step:
//     z  = relu(A1[t] + deq(l1h) @ h)
//     y2 = deq(l2) @ z + l2_b
//     temp = relu([XI[t], h] + y2);  h' = deq(xh2h) @ temp + xh2h_b
//  K3 (GEMM fp32):  ys[t] = out_w @ Hs[t] + out_b

#define T_    512
#define IND   1024
#define HD    2048
#define H2    4096
#define OUTD  1024
#define NCTA  148
#define NTHR  1024

typedef unsigned long long ull;

__device__ float g_XI[T_ * HD];
__device__ float g_A1[T_ * H2];
__device__ float g_Hs[T_ * HD];
__device__ float g_z [H2];
__device__ float g_y2[H2];
__device__ unsigned g_bar  = 0;
__device__ unsigned g_rel  = 0;
__device__ unsigned g_done = 0;

// Quantized weights (biased uint16: stored = q + 32768) + per-row scales
__device__ unsigned short g_qL1h[(size_t)H2 * HD];
__device__ unsigned short g_qL2 [(size_t)H2 * H2];
__device__ unsigned short g_qXh [(size_t)HD * H2];
__device__ float g_sL1h[H2];
__device__ float g_sL2 [H2];
__device__ float g_sXh [HD];

// ---------------------------------------------------------------------------
// fp32 GEMM:  C[M,N] = A[M,K] * B[N,K]^T + bias[N]   (64x64x16 tiles)
// ---------------------------------------------------------------------------
__global__ void __launch_bounds__(256) gemm_tt(
    const float* __restrict__ A, int lda,
    const float* __restrict__ B, int ldb,
    const float* __restrict__ bias,
    float* __restrict__ C, int ldc,
    int K)
{
    __shared__ float As[16][65];
    __shared__ float Bs[16][65];
    const int tx = threadIdx.x & 15;
    const int ty = threadIdx.x >> 4;
    const int m0 = blockIdx.y * 64;
    const int n0 = blockIdx.x * 64;

    float acc[4][4] = {};

    for (int k0 = 0; k0 < K; k0 += 16) {
#pragma unroll
        for (int i = threadIdx.x; i < 1024; i += 256) {
            int r  = i >> 4;
            int kk = i & 15;
            As[kk][r] = A[(size_t)(m0 + r) * lda + k0 + kk];
            Bs[kk][r] = B[(size_t)(n0 + r) * ldb + k0 + kk];
        }
        __syncthreads();
#pragma unroll
        for (int kk = 0; kk < 16; kk++) {
            float a[4], b[4];
#pragma unroll
            for (int i = 0; i < 4; i++) a[i] = As[kk][ty * 4 + i];
#pragma unroll
            for (int j = 0; j < 4; j++) b[j] = Bs[kk][tx * 4 + j];
#pragma unroll
            for (int i = 0; i < 4; i++)
#pragma unroll
                for (int j = 0; j < 4; j++)
                    acc[i][j] = fmaf(a[i], b[j], acc[i][j]);
        }
        __syncthreads();
    }

#pragma unroll
    for (int i = 0; i < 4; i++) {
        int m = m0 + ty * 4 + i;
#pragma unroll
        for (int j = 0; j < 4; j++) {
            int n = n0 + tx * 4 + j;
            C[(size_t)m * ldc + n] = acc[i][j] + bias[n];
        }
    }
}

// ---------------------------------------------------------------------------
// Per-row symmetric int16 quantization (deterministic; rerun each launch).
// ---------------------------------------------------------------------------
__global__ void __launch_bounds__(256) quantize_rows(
    const float* __restrict__ src, int ld, int col0, int ncols,
    unsigned short* __restrict__ dst, float* __restrict__ scales)
{
    const int r = blockIdx.x;
    const float* row = src + (size_t)r * ld + col0;
    __shared__ float red[256];

    float m = 0.f;
    for (int i = threadIdx.x; i < ncols; i += 256)
        m = fmaxf(m, fabsf(row[i]));
    red[threadIdx.x] = m;
    __syncthreads();
    for (int s = 128; s; s >>= 1) {
        if (threadIdx.x < s)
            red[threadIdx.x] = fmaxf(red[threadIdx.x], red[threadIdx.x + s]);
        __syncthreads();
    }
    const float mx  = red[0];
    const float inv = (mx > 0.f) ? 32767.0f / mx : 0.f;
    if (threadIdx.x == 0)
        scales[r] = (mx > 0.f) ? mx / 32767.0f : 1.0f;

    unsigned short* drow = dst + (size_t)r * ncols;
    for (int i = threadIdx.x; i < ncols; i += 256) {
        int q = __float2int_rn(row[i] * inv);
        drow[i] = (unsigned short)(q + 32768);
    }
}

// ---------------------------------------------------------------------------
// f32x2 helpers
// ---------------------------------------------------------------------------
__device__ __forceinline__ ull pack2(unsigned lo, unsigned hi) {
    ull r;
    asm("mov.b64 %0, {%1, %2};" : "=l"(r) : "r"(lo), "r"(hi));
    return r;
}
__device__ __forceinline__ ull add2(ull a, ull b) {
    ull r;
    asm("add.rn.f32x2 %0, %1, %2;" : "=l"(r) : "l"(a), "l"(b));
    return r;
}
__device__ __forceinline__ ull fma2(ull a, ull b, ull c) {
    ull r;
    asm("fma.rn.f32x2 %0, %1, %2, %3;" : "=l"(r) : "l"(a), "l"(b), "l"(c));
    return r;
}

__device__ __forceinline__ float warp_red(float v) {
#pragma unroll
    for (int o = 16; o; o >>= 1) v += __shfl_down_sync(0xffffffffu, v, o);
    return v;
}

// -8421376.0f (= -(2^23 + 2^15)) in both lanes
#define NMAG2 0xCB008000CB008000ull

// dequant-dot over NU4 uint4s (8 biased-u16 weights each) against swizzled
// shared x (float4 element j stored at j ^ ((j>>3)&7)). ioff = starting uint4
// index within the logical row (for half-row tasks).
template <int NU4>
__device__ __forceinline__ float dotq(const uint4* __restrict__ qrow,
                                      const float4* __restrict__ xs,
                                      int lane, int ioff)
{
    const ulonglong2* x2 = reinterpret_cast<const ulonglong2*>(xs);
    ull acc0 = 0, acc1 = 0;
#pragma unroll 4
    for (int k = 0; k < NU4 / 32; k++) {
        int i = ioff + lane + 32 * k;
        uint4 w = __ldcg(qrow + lane + 32 * k);
        int sw = (i >> 2) & 7;
        ulonglong2 X0 = x2[(2 * i) ^ sw];
        ulonglong2 X1 = x2[(2 * i) ^ sw ^ 1];
        ull d;
        d = add2(pack2(__byte_perm(w.x, 0x4B000000u, 0x7410),
                       __byte_perm(w.x, 0x4B000000u, 0x7432)), NMAG2);
        acc0 = fma2(d, X0.x, acc0);
        d = add2(pack2(__byte_perm(w.y, 0x4B000000u, 0x7410),
                       __byte_perm(w.y, 0x4B000000u, 0x7432)), NMAG2);
        acc1 = fma2(d, X0.y, acc1);
        d = add2(pack2(__byte_perm(w.z, 0x4B000000u, 0x7410),
                       __byte_perm(w.z, 0x4B000000u, 0x7432)), NMAG2);
        acc0 = fma2(d, X1.x, acc0);
        d = add2(pack2(__byte_perm(w.w, 0x4B000000u, 0x7410),
                       __byte_perm(w.w, 0x4B000000u, 0x7432)), NMAG2);
        acc1 = fma2(d, X1.y, acc1);
    }
    acc0 = add2(acc0, acc1);
    unsigned lo, hi;
    asm("mov.b64 {%0, %1}, %2;" : "=r"(lo), "=r"(hi) : "l"(acc0));
    float s = __uint_as_float(lo) + __uint_as_float(hi);
    return warp_red(s);
}

// ---------------------------------------------------------------------------
// Grid barrier: contended arrival counter + separate read-only release word.
// ---------------------------------------------------------------------------
#define GRID_SYNC() do {                                                      \
    __syncthreads();                                                          \
    if (tid == 0) {                                                           \
        __threadfence();                                                      \
        ep++;                                                                 \
        unsigned a = atomicAdd(&g_bar, 1u) + 1u;                              \
        if (a == ep * (unsigned)NCTA) {                                       \
            __threadfence();                                                  \
            atomicExch(&g_rel, ep);                                           \
        } else {                                                              \
            unsigned v;                                                       \
            do {                                                              \
                asm volatile("ld.global.acquire.gpu.u32 %0, [%1];"            \
                             : "=r"(v) : "l"(&g_rel));                        \
            } while (v < ep);                                                 \
        }                                                                     \
    }                                                                         \
    __syncthreads();                                                          \
} while (0)

__global__ void __launch_bounds__(NTHR, 1) resrnn_seq(
    const float* __restrict__ h0,
    const float* __restrict__ l2b,
    const float* __restrict__ xh2hb)
{
    __shared__ float4 hs4[HD / 4];     //  8 KB: h_prev, swizzled
    __shared__ float4 sb4[H2 / 4];     // 16 KB: phase input vector, swizzled
    __shared__ float  spart[32];       // phase-C half-row partials
    const int tid  = threadIdx.x;
    const int wid  = tid >> 5;
    const int lane = tid & 31;
    const int bid  = blockIdx.x;
    const int r    = bid + NCTA * wid;              // phase A/B row
    const int crow = bid + NCTA * (wid >> 1);       // phase C row
    const int chal = wid & 1;                       // phase C half
    unsigned  ep   = 0;

    for (int t = 0; t < T_; t++) {
        const float4* hprev4 = (t == 0)
            ? reinterpret_cast<const float4*>(h0)
            : reinterpret_cast<const float4*>(&g_Hs[(size_t)(t - 1) * HD]);

        // ---- stage h_prev (swizzled) ----
        for (int j = tid; j < HD / 4; j += NTHR)
            hs4[j ^ ((j >> 3) & 7)] = hprev4[j];
        __syncthreads();

        // ---- Phase A: z = relu(A1[t] + l1h @ h) ----
        if (r < H2) {
            const uint4* qrow = reinterpret_cast<const uint4*>(
                g_qL1h + (size_t)r * HD);
            float s = dotq<HD / 8>(qrow, hs4, lane, 0);
            if (lane == 0) {
                float zz = g_A1[(size_t)t * H2 + r] + g_sL1h[r] * s;
                g_z[r] = fmaxf(zz, 0.f);
            }
        }
        GRID_SYNC();

        // ---- Phase B: y2 = l2 @ z + l2_b ----
        {
            const float4* z4 = reinterpret_cast<const float4*>(g_z);
            for (int j = tid; j < H2 / 4; j += NTHR)
                sb4[j ^ ((j >> 3) & 7)] = z4[j];
        }
        __syncthreads();
        if (r < H2) {
            const uint4* qrow = reinterpret_cast<const uint4*>(
                g_qL2 + (size_t)r * H2);
            float s = dotq<H2 / 8>(qrow, sb4, lane, 0);
            if (lane == 0) g_y2[r] = g_sL2[r] * s + l2b[r];
        }
        GRID_SYNC();

        // ---- Phase C: temp = relu(xh + y2); h' = xh2h @ temp + b ----
        {
            const float4* xi4 = reinterpret_cast<const float4*>(
                &g_XI[(size_t)t * HD]);
            const float4* y4 = reinterpret_cast<const float4*>(g_y2);
            for (int j = tid; j < H2 / 4; j += NTHR) {
                float4 xh;
                if (j < HD / 4) {
                    xh = xi4[j];
                } else {
                    int jj = j - HD / 4;
                    xh = hs4[jj ^ ((jj >> 3) & 7)];
                }
                float4 y = y4[j];
                float4 tv;
                tv.x = fmaxf(xh.x + y.x, 0.f);
                tv.y = fmaxf(xh.y + y.y, 0.f);
                tv.z = fmaxf(xh.z + y.z, 0.f);
                tv.w = fmaxf(xh.w + y.w, 0.f);
                sb4[j ^ ((j >> 3) & 7)] = tv;
            }
        }
        __syncthreads();
        // half-row tasks: two adjacent warps share one output row
        if (crow < HD) {
            const uint4* qrow = reinterpret_cast<const uint4*>(
                g_qXh + (size_t)crow * H2) + chal * (HD / 8);
            float s = dotq<HD / 8>(qrow, sb4, lane, chal * (HD / 8));
            if (lane == 0) spart[wid] = s;
        }
        __syncthreads();
        if (crow < HD && chal == 0 && lane == 0) {
            float s = spart[wid] + spart[wid + 1];
            g_Hs[(size_t)t * HD + crow] = g_sXh[crow] * s + xh2hb[crow];
        }
        GRID_SYNC();
    }

    // Reset barrier state for next graph replay (handshake first).
    if (tid == 0) {
        __threadfence();
        atomicAdd(&g_done, 1u);
        if (bid == 0) {
            unsigned v;
            while (1) {
                asm volatile("ld.global.acquire.gpu.u32 %0, [%1];"
                             : "=r"(v) : "l"(&g_done));
                if (v >= (unsigned)NCTA) break;
                __nanosleep(64);
            }
            g_bar  = 0u;
            g_rel  = 0u;
            g_done = 0u;
            __threadfence();
        }
    }
}

__global__ void copy_hfinal(float* __restrict__ out)
{
    int i = blockIdx.x * blockDim.x + threadIdx.x;
    if (i < HD) out[i] = g_Hs[(size_t)(T_ - 1) * HD + i];
}

// ---------------------------------------------------------------------------
extern "C" void kernel_launch(void* const* d_in, const int* in_sizes, int n_in,
                              void* d_out, int out_size)
{
    const float* x      = (const float*)d_in[0];
    const float* h0     = (const float*)d_in[1];
    const float* inp_w  = (const float*)d_in[2];
    const float* inp_b  = (const float*)d_in[3];
    const float* l1_w   = (const float*)d_in[4];
    const float* l1_b   = (const float*)d_in[5];
    const float* l2_w   = (const float*)d_in[6];
    const float* l2_b   = (const float*)d_in[7];
    const float* xh2h_w = (const float*)d_in[8];
    const float* xh2h_b = (const float*)d_in[9];
    const float* out_w  = (const float*)d_in[10];
    const float* out_b  = (const float*)d_in[11];

    float *pXI, *pA1, *pHs, *pSL1h, *pSL2, *pSXh;
    unsigned short *pQL1h, *pQL2, *pQXh;
    cudaGetSymbolAddress((void**)&pXI,   g_XI);
    cudaGetSymbolAddress((void**)&pA1,   g_A1);
    cudaGetSymbolAddress((void**)&pHs,   g_Hs);
    cudaGetSymbolAddress((void**)&pQL1h, g_qL1h);
    cudaGetSymbolAddress((void**)&pQL2,  g_qL2);
    cudaGetSymbolAddress((void**)&pQXh,  g_qXh);
    cudaGetSymbolAddress((void**)&pSL1h, g_sL1h);
    cudaGetSymbolAddress((void**)&pSL2,  g_sL2);
    cudaGetSymbolAddress((void**)&pSXh,  g_sXh);

    // Quantize recurrent weights (int16 + per-row scale)
    quantize_rows<<<H2, 256>>>(l1_w,   H2, HD, HD, pQL1h, pSL1h);
    quantize_rows<<<H2, 256>>>(l2_w,   H2, 0,  H2, pQL2,  pSL2);
    quantize_rows<<<HD, 256>>>(xh2h_w, H2, 0,  H2, pQXh,  pSXh);

    // K1: XI[512,2048] = x * inp_w^T + inp_b
    gemm_tt<<<dim3(HD / 64, T_ / 64), 256>>>(x, IND, inp_w, IND, inp_b,
                                             pXI, HD, IND);
    // K2: A1[512,4096] = XI * l1_w[:, :2048]^T + l1_b
    gemm_tt<<<dim3(H2 / 64, T_ / 64), 256>>>(pXI, HD, l1_w, H2, l1_b,
                                             pA1, H2, HD);
    // Sequential recurrence
    resrnn_seq<<<NCTA, NTHR>>>(h0, l2_b, xh2h_b);

    // K3: ys[512,1024] = Hs * out_w^T + out_b
    gemm_tt<<<dim3(OUTD / 64, T_ / 64), 256>>>(pHs, HD, out_w, HD, out_b,
                                               (float*)d_out, OUTD, HD);

    if (out_size >= T_ * OUTD + HD) {
        copy_hfinal<<<2, NTHR>>>((float*)d_out + (size_t)T_ * OUTD);
    }
}

// round 4
// speedup vs baseline: 1.0795x; 1.0795x over previous
#include <cuda_runtime.h>
#include <cstdint>

// ResRNN with int16-quantized recurrent weights (R2 structure) + L1-pinned
// weight subset: each warp's rows are fixed across the 512 steps, so a
// ~160KB/SM slice is loaded with ld.ca (L1-resident across steps) while the
// rest streams with ld.cg. All activation loads are ld.cg so they cannot
// evict the pinned lines.

#define T_    512
#define IND   1024
#define HD    2048
#define H2    4096
#define OUTD  1024
#define NCTA  148
#define NTHR  1024

__device__ float g_XI[T_ * HD];   // 4 MB
__device__ float g_A1[T_ * H2];   // 8 MB
__device__ float g_Hs[T_ * HD];   // 4 MB
__device__ float g_z [H2];
__device__ float g_y2[H2];
__device__ unsigned g_bar  = 0;
__device__ unsigned g_done = 0;

// Quantized weights (biased uint16: stored = q + 32768) + per-row scales
__device__ unsigned short g_qL1h[(size_t)H2 * HD];  // 16 MB
__device__ unsigned short g_qL2 [(size_t)H2 * H2];  // 32 MB
__device__ unsigned short g_qXh [(size_t)HD * H2];  // 16 MB
__device__ float g_sL1h[H2];
__device__ float g_sL2 [H2];
__device__ float g_sXh [HD];

// ---------------------------------------------------------------------------
// fp32 GEMM:  C[M,N] = A[M,K] * B[N,K]^T + bias[N]   (64x64x16 tiles)
// ---------------------------------------------------------------------------
__global__ void __launch_bounds__(256) gemm_tt(
    const float* __restrict__ A, int lda,
    const float* __restrict__ B, int ldb,
    const float* __restrict__ bias,
    float* __restrict__ C, int ldc,
    int K)
{
    __shared__ float As[16][65];
    __shared__ float Bs[16][65];
    const int tx = threadIdx.x & 15;
    const int ty = threadIdx.x >> 4;
    const int m0 = blockIdx.y * 64;
    const int n0 = blockIdx.x * 64;

    float acc[4][4] = {};

    for (int k0 = 0; k0 < K; k0 += 16) {
#pragma unroll
        for (int i = threadIdx.x; i < 1024; i += 256) {
            int r  = i >> 4;
            int kk = i & 15;
            As[kk][r] = A[(size_t)(m0 + r) * lda + k0 + kk];
            Bs[kk][r] = B[(size_t)(n0 + r) * ldb + k0 + kk];
        }
        __syncthreads();
#pragma unroll
        for (int kk = 0; kk < 16; kk++) {
            float a[4], b[4];
#pragma unroll
            for (int i = 0; i < 4; i++) a[i] = As[kk][ty * 4 + i];
#pragma unroll
            for (int j = 0; j < 4; j++) b[j] = Bs[kk][tx * 4 + j];
#pragma unroll
            for (int i = 0; i < 4; i++)
#pragma unroll
                for (int j = 0; j < 4; j++)
                    acc[i][j] = fmaf(a[i], b[j], acc[i][j]);
        }
        __syncthreads();
    }

#pragma unroll
    for (int i = 0; i < 4; i++) {
        int m = m0 + ty * 4 + i;
#pragma unroll
        for (int j = 0; j < 4; j++) {
            int n = n0 + tx * 4 + j;
            C[(size_t)m * ldc + n] = acc[i][j] + bias[n];
        }
    }
}

// ---------------------------------------------------------------------------
// Per-row symmetric int16 quantization (deterministic; rerun each launch).
// ---------------------------------------------------------------------------
__global__ void __launch_bounds__(256) quantize_rows(
    const float* __restrict__ src, int ld, int col0, int ncols,
    unsigned short* __restrict__ dst, float* __restrict__ scales)
{
    const int r = blockIdx.x;
    const float* row = src + (size_t)r * ld + col0;
    __shared__ float red[256];

    float m = 0.f;
    for (int i = threadIdx.x; i < ncols; i += 256)
        m = fmaxf(m, fabsf(row[i]));
    red[threadIdx.x] = m;
    __syncthreads();
    for (int s = 128; s; s >>= 1) {
        if (threadIdx.x < s)
            red[threadIdx.x] = fmaxf(red[threadIdx.x], red[threadIdx.x + s]);
        __syncthreads();
    }
    const float mx  = red[0];
    const float inv = (mx > 0.f) ? 32767.0f / mx : 0.f;
    if (threadIdx.x == 0)
        scales[r] = (mx > 0.f) ? mx / 32767.0f : 1.0f;

    unsigned short* drow = dst + (size_t)r * ncols;
    for (int i = threadIdx.x; i < ncols; i += 256) {
        int q = __float2int_rn(row[i] * inv);
        drow[i] = (unsigned short)(q + 32768);
    }
}

// ---------------------------------------------------------------------------
// Persistent sequential kernel
// ---------------------------------------------------------------------------
__device__ __forceinline__ float warp_red(float v) {
#pragma unroll
    for (int o = 16; o; o >>= 1) v += __shfl_down_sync(0xffffffffu, v, o);
    return v;
}

// dequant-dot: N16 uint4s (8 biased-u16 weights each) vs swizzled shared x
// (float4 element j stored at j ^ ((j>>3)&7)).
// First CA iterations use ld.ca (pinned in L1 across steps), rest ld.cg.
#define CVT_MAGIC 8421376.0f
template <int N16, int CA>
__device__ __forceinline__ float dotq(const uint4* __restrict__ qrow,
                                      const float4* __restrict__ xs,
                                      int lane)
{
    float s = 0.f;
#pragma unroll 4
    for (int k = 0; k < N16 / 32; k++) {
        int i = lane + 32 * k;
        uint4 w = (k < CA) ? __ldca(qrow + i) : __ldcg(qrow + i);
        int sw = (i >> 2) & 7;               // ((2i)>>3)&7
        float4 x0 = xs[(2 * i) ^ sw];
        float4 x1 = xs[(2 * i) ^ sw ^ 1];
        float f;
        f = __uint_as_float(__byte_perm(w.x, 0x4B000000u, 0x7410)) - CVT_MAGIC;
        s = fmaf(f, x0.x, s);
        f = __uint_as_float(__byte_perm(w.x, 0x4B000000u, 0x7432)) - CVT_MAGIC;
        s = fmaf(f, x0.y, s);
        f = __uint_as_float(__byte_perm(w.y, 0x4B000000u, 0x7410)) - CVT_MAGIC;
        s = fmaf(f, x0.z, s);
        f = __uint_as_float(__byte_perm(w.y, 0x4B000000u, 0x7432)) - CVT_MAGIC;
        s = fmaf(f, x0.w, s);
        f = __uint_as_float(__byte_perm(w.z, 0x4B000000u, 0x7410)) - CVT_MAGIC;
        s = fmaf(f, x1.x, s);
        f = __uint_as_float(__byte_perm(w.z, 0x4B000000u, 0x7432)) - CVT_MAGIC;
        s = fmaf(f, x1.y, s);
        f = __uint_as_float(__byte_perm(w.w, 0x4B000000u, 0x7410)) - CVT_MAGIC;
        s = fmaf(f, x1.z, s);
        f = __uint_as_float(__byte_perm(w.w, 0x4B000000u, 0x7432)) - CVT_MAGIC;
        s = fmaf(f, x1.w, s);
    }
    return warp_red(s);
}

#define GRID_SYNC() do {                                                      \
    __syncthreads();                                                          \
    if (tid == 0) {                                                           \
        __threadfence();                                                      \
        atomicAdd(&g_bar, 1u);                                                \
        ep++;                                                                 \
        unsigned tgt = ep * (unsigned)NCTA;                                   \
        unsigned v;                                                           \
        while (1) {                                                           \
            asm volatile("ld.global.acquire.gpu.u32 %0, [%1];"                \
                         : "=r"(v) : "l"(&g_bar));                            \
            if (v >= tgt) break;                                              \
            __nanosleep(32);                                                  \
        }                                                                     \
    }                                                                         \
    __syncthreads();                                                          \
} while (0)

__global__ void __launch_bounds__(NTHR, 1) resrnn_seq(
    const float* __restrict__ h0,
    const float* __restrict__ l2b,
    const float* __restrict__ xh2hb)
{
    __shared__ float4 hs4[HD / 4];   //  8 KB: h_prev, swizzled
    __shared__ float4 sb4[H2 / 4];   // 16 KB: phase input vector, swizzled
    const int tid  = threadIdx.x;
    const int wid  = tid >> 5;
    const int lane = tid & 31;
    const int bid  = blockIdx.x;
    const int r    = bid + NCTA * wid;   // this warp's output row
    unsigned  ep   = 0;

    for (int t = 0; t < T_; t++) {
        const float4* hprev4 = (t == 0)
            ? reinterpret_cast<const float4*>(h0)
            : reinterpret_cast<const float4*>(&g_Hs[(size_t)(t - 1) * HD]);

        // ---- stage h_prev (swizzled); ld.cg: don't pollute pinned L1 ----
        for (int j = tid; j < HD / 4; j += NTHR)
            hs4[j ^ ((j >> 3) & 7)] = __ldcg(hprev4 + j);
        __syncthreads();

        // ---- Phase A: z = relu(A1[t] + l1h @ h) -- fully L1-pinned ----
        if (r < H2) {
            const uint4* qrow = reinterpret_cast<const uint4*>(
                g_qL1h + (size_t)r * HD);
            float s = dotq<HD / 8, 8>(qrow, hs4, lane);   // 8/8 iters ca
            if (lane == 0) {
                float zz = __ldcg(&g_A1[(size_t)t * H2 + r]) + g_sL1h[r] * s;
                g_z[r] = fmaxf(zz, 0.f);
            }
        }
        GRID_SYNC();

        // ---- Phase B: y2 = l2 @ z + l2_b -- first 2/16 iters pinned ----
        {
            const float4* z4 = reinterpret_cast<const float4*>(g_z);
            for (int j = tid; j < H2 / 4; j += NTHR)
                sb4[j ^ ((j >> 3) & 7)] = __ldcg(z4 + j);
        }
        __syncthreads();
        if (r < H2) {
            const uint4* qrow = reinterpret_cast<const uint4*>(
                g_qL2 + (size_t)r * H2);
            float s = dotq<H2 / 8, 2>(qrow, sb4, lane);
            if (lane == 0) g_y2[r] = g_sL2[r] * s + __ldcg(l2b + r);
        }
        GRID_SYNC();

        // ---- Phase C: temp = relu(xh + y2); h' = xh2h @ temp + b ----
        {
            const float4* xi4 = reinterpret_cast<const float4*>(
                &g_XI[(size_t)t * HD]);
            const float4* y4 = reinterpret_cast<const float4*>(g_y2);
            for (int j = tid; j < H2 / 4; j += NTHR) {
                float4 xh;
                if (j < HD / 4) {
                    xh = __ldcg(xi4 + j);
                } else {
                    int jj = j - HD / 4;
                    xh = hs4[jj ^ ((jj >> 3) & 7)];   // unswizzle h
                }
                float4 y = __ldcg(y4 + j);
                float4 tv;
                tv.x = fmaxf(xh.x + y.x, 0.f);
                tv.y = fmaxf(xh.y + y.y, 0.f);
                tv.z = fmaxf(xh.z + y.z, 0.f);
                tv.w = fmaxf(xh.w + y.w, 0.f);
                sb4[j ^ ((j >> 3) & 7)] = tv;
            }
        }
        __syncthreads();
        if (r < HD) {
            const uint4* qrow = reinterpret_cast<const uint4*>(
                g_qXh + (size_t)r * H2);
            float s = dotq<H2 / 8, 0>(qrow, sb4, lane);   // streamed
            if (lane == 0)
                g_Hs[(size_t)t * HD + r] = g_sXh[r] * s + __ldcg(xh2hb + r);
        }
        GRID_SYNC();
    }

    // Reset barrier for next graph replay (handshake: nobody still spinning).
    if (tid == 0) {
        __threadfence();
        atomicAdd(&g_done, 1u);
        if (bid == 0) {
            unsigned v;
            while (1) {
                asm volatile("ld.global.acquire.gpu.u32 %0, [%1];"
                             : "=r"(v) : "l"(&g_done));
                if (v >= (unsigned)NCTA) break;
                __nanosleep(64);
            }
            g_bar  = 0u;
            g_done = 0u;
            __threadfence();
        }
    }
}

__global__ void copy_hfinal(float* __restrict__ out)
{
    int i = blockIdx.x * blockDim.x + threadIdx.x;
    if (i < HD) out[i] = g_Hs[(size_t)(T_ - 1) * HD + i];
}

// ---------------------------------------------------------------------------
extern "C" void kernel_launch(void* const* d_in, const int* in_sizes, int n_in,
                              void* d_out, int out_size)
{
    const float* x      = (const float*)d_in[0];
    const float* h0     = (const float*)d_in[1];
    const float* inp_w  = (const float*)d_in[2];
    const float* inp_b  = (const float*)d_in[3];
    const float* l1_w   = (const float*)d_in[4];
    const float* l1_b   = (const float*)d_in[5];
    const float* l2_w   = (const float*)d_in[6];
    const float* l2_b   = (const float*)d_in[7];
    const float* xh2h_w = (const float*)d_in[8];
    const float* xh2h_b = (const float*)d_in[9];
    const float* out_w  = (const float*)d_in[10];
    const float* out_b  = (const float*)d_in[11];

    float *pXI, *pA1, *pHs, *pSL1h, *pSL2, *pSXh;
    unsigned short *pQL1h, *pQL2, *pQXh;
    cudaGetSymbolAddress((void**)&pXI,   g_XI);
    cudaGetSymbolAddress((void**)&pA1,   g_A1);
    cudaGetSymbolAddress((void**)&pHs,   g_Hs);
    cudaGetSymbolAddress((void**)&pQL1h, g_qL1h);
    cudaGetSymbolAddress((void**)&pQL2,  g_qL2);
    cudaGetSymbolAddress((void**)&pQXh,  g_qXh);
    cudaGetSymbolAddress((void**)&pSL1h, g_sL1h);
    cudaGetSymbolAddress((void**)&pSL2,  g_sL2);
    cudaGetSymbolAddress((void**)&pSXh,  g_sXh);

    // Quantize recurrent weights (int16 + per-row scale)
    quantize_rows<<<H2, 256>>>(l1_w,   H2, HD, HD, pQL1h, pSL1h);
    quantize_rows<<<H2, 256>>>(l2_w,   H2, 0,  H2, pQL2,  pSL2);
    quantize_rows<<<HD, 256>>>(xh2h_w, H2, 0,  H2, pQXh,  pSXh);

    // K1: XI[512,2048] = x * inp_w^T + inp_b
    gemm_tt<<<dim3(HD / 64, T_ / 64), 256>>>(x, IND, inp_w, IND, inp_b,
                                             pXI, HD, IND);
    // K2: A1[512,4096] = XI * l1_w[:, :2048]^T + l1_b
    gemm_tt<<<dim3(H2 / 64, T_ / 64), 256>>>(pXI, HD, l1_w, H2, l1_b,
                                             pA1, H2, HD);
    // Sequential recurrence
    resrnn_seq<<<NCTA, NTHR>>>(h0, l2_b, xh2h_b);

    // K3: ys[512,1024] = Hs * out_w^T + out_b
    gemm_tt<<<dim3(OUTD / 64, T_ / 64), 256>>>(pHs, HD, out_w, HD, out_b,
                                               (float*)d_out, OUTD, HD);

    if (out_size >= T_ * OUTD + HD) {
        copy_hfinal<<<2, NTHR>>>((float*)d_out + (size_t)T_ * OUTD);
    }
}

// round 5
// speedup vs baseline: 1.1405x; 1.0566x over previous
#include <cuda_runtime.h>
#include <cstdint>

// ResRNN, int16-quantized recurrent weights (R2 structure), f32x2 packed
// dequant-FMA + cross-barrier weight prefetch. Barrier identical to R2.

#define T_    512
#define IND   1024
#define HD    2048
#define H2    4096
#define OUTD  1024
#define NCTA  148
#define NTHR  1024

typedef unsigned long long ull;

__device__ float g_XI[T_ * HD];
__device__ float g_A1[T_ * H2];
__device__ float g_Hs[T_ * HD];
__device__ float g_z [H2];
__device__ float g_y2[H2];
__device__ unsigned g_bar  = 0;
__device__ unsigned g_done = 0;

__device__ unsigned short g_qL1h[(size_t)H2 * HD];
__device__ unsigned short g_qL2 [(size_t)H2 * H2];
__device__ unsigned short g_qXh [(size_t)HD * H2];
__device__ float g_sL1h[H2];
__device__ float g_sL2 [H2];
__device__ float g_sXh [HD];

// ---------------------------------------------------------------------------
// fp32 GEMM:  C[M,N] = A[M,K] * B[N,K]^T + bias[N]   (64x64x16 tiles)
// ---------------------------------------------------------------------------
__global__ void __launch_bounds__(256) gemm_tt(
    const float* __restrict__ A, int lda,
    const float* __restrict__ B, int ldb,
    const float* __restrict__ bias,
    float* __restrict__ C, int ldc,
    int K)
{
    __shared__ float As[16][65];
    __shared__ float Bs[16][65];
    const int tx = threadIdx.x & 15;
    const int ty = threadIdx.x >> 4;
    const int m0 = blockIdx.y * 64;
    const int n0 = blockIdx.x * 64;

    float acc[4][4] = {};

    for (int k0 = 0; k0 < K; k0 += 16) {
#pragma unroll
        for (int i = threadIdx.x; i < 1024; i += 256) {
            int r  = i >> 4;
            int kk = i & 15;
            As[kk][r] = A[(size_t)(m0 + r) * lda + k0 + kk];
            Bs[kk][r] = B[(size_t)(n0 + r) * ldb + k0 + kk];
        }
        __syncthreads();
#pragma unroll
        for (int kk = 0; kk < 16; kk++) {
            float a[4], b[4];
#pragma unroll
            for (int i = 0; i < 4; i++) a[i] = As[kk][ty * 4 + i];
#pragma unroll
            for (int j = 0; j < 4; j++) b[j] = Bs[kk][tx * 4 + j];
#pragma unroll
            for (int i = 0; i < 4; i++)
#pragma unroll
                for (int j = 0; j < 4; j++)
                    acc[i][j] = fmaf(a[i], b[j], acc[i][j]);
        }
        __syncthreads();
    }

#pragma unroll
    for (int i = 0; i < 4; i++) {
        int m = m0 + ty * 4 + i;
#pragma unroll
        for (int j = 0; j < 4; j++) {
            int n = n0 + tx * 4 + j;
            C[(size_t)m * ldc + n] = acc[i][j] + bias[n];
        }
    }
}

// ---------------------------------------------------------------------------
// Per-row symmetric int16 quantization (deterministic; rerun each launch).
// ---------------------------------------------------------------------------
__global__ void __launch_bounds__(256) quantize_rows(
    const float* __restrict__ src, int ld, int col0, int ncols,
    unsigned short* __restrict__ dst, float* __restrict__ scales)
{
    const int r = blockIdx.x;
    const float* row = src + (size_t)r * ld + col0;
    __shared__ float red[256];

    float m = 0.f;
    for (int i = threadIdx.x; i < ncols; i += 256)
        m = fmaxf(m, fabsf(row[i]));
    red[threadIdx.x] = m;
    __syncthreads();
    for (int s = 128; s; s >>= 1) {
        if (threadIdx.x < s)
            red[threadIdx.x] = fmaxf(red[threadIdx.x], red[threadIdx.x + s]);
        __syncthreads();
    }
    const float mx  = red[0];
    const float inv = (mx > 0.f) ? 32767.0f / mx : 0.f;
    if (threadIdx.x == 0)
        scales[r] = (mx > 0.f) ? mx / 32767.0f : 1.0f;

    unsigned short* drow = dst + (size_t)r * ncols;
    for (int i = threadIdx.x; i < ncols; i += 256) {
        int q = __float2int_rn(row[i] * inv);
        drow[i] = (unsigned short)(q + 32768);
    }
}

// ---------------------------------------------------------------------------
// f32x2 helpers
// ---------------------------------------------------------------------------
__device__ __forceinline__ ull pack2(unsigned lo, unsigned hi) {
    ull r;
    asm("mov.b64 %0, {%1, %2};" : "=l"(r) : "r"(lo), "r"(hi));
    return r;
}
__device__ __forceinline__ ull add2(ull a, ull b) {
    ull r;
    asm("add.rn.f32x2 %0, %1, %2;" : "=l"(r) : "l"(a), "l"(b));
    return r;
}
__device__ __forceinline__ ull fma2(ull a, ull b, ull c) {
    ull r;
    asm("fma.rn.f32x2 %0, %1, %2, %3;" : "=l"(r) : "l"(a), "l"(b), "l"(c));
    return r;
}

__device__ __forceinline__ float warp_red(float v) {
#pragma unroll
    for (int o = 16; o; o >>= 1) v += __shfl_down_sync(0xffffffffu, v, o);
    return v;
}

// -8421376.0f (= -(2^23 + 2^15)) in both lanes
#define NMAG2 0xCB008000CB008000ull

// process 8 biased-u16 weights (one uint4) at logical uint4-index i against
// swizzled shared x (ulonglong2 view; float4 elem j stored at j^((j>>3)&7)).
__device__ __forceinline__ void proc8(uint4 w, int i,
                                      const ulonglong2* __restrict__ x2,
                                      ull& a0, ull& a1)
{
    int sw = (i >> 2) & 7;
    ulonglong2 X0 = x2[(2 * i) ^ sw];
    ulonglong2 X1 = x2[(2 * i) ^ sw ^ 1];
    a0 = fma2(add2(pack2(__byte_perm(w.x, 0x4B000000u, 0x7410),
                         __byte_perm(w.x, 0x4B000000u, 0x7432)), NMAG2),
              X0.x, a0);
    a1 = fma2(add2(pack2(__byte_perm(w.y, 0x4B000000u, 0x7410),
                         __byte_perm(w.y, 0x4B000000u, 0x7432)), NMAG2),
              X0.y, a1);
    a0 = fma2(add2(pack2(__byte_perm(w.z, 0x4B000000u, 0x7410),
                         __byte_perm(w.z, 0x4B000000u, 0x7432)), NMAG2),
              X1.x, a0);
    a1 = fma2(add2(pack2(__byte_perm(w.w, 0x4B000000u, 0x7410),
                         __byte_perm(w.w, 0x4B000000u, 0x7432)), NMAG2),
              X1.y, a1);
}

// dequant-dot: N16 uint4s per row; first two uint4s come prefetched (loaded
// before the previous grid barrier), rest stream with ld.cg.
template <int N16>
__device__ __forceinline__ float dotq2(const uint4* __restrict__ qrow,
                                       const float4* __restrict__ xs,
                                       int lane, uint4 pf0, uint4 pf1)
{
    const ulonglong2* x2 = reinterpret_cast<const ulonglong2*>(xs);
    ull a0 = 0, a1 = 0;
    proc8(pf0, lane,      x2, a0, a1);
    proc8(pf1, lane + 32, x2, a0, a1);
#pragma unroll 4
    for (int k = 2; k < N16 / 32; k++) {
        int i = lane + 32 * k;
        uint4 w = __ldcg(qrow + i);
        proc8(w, i, x2, a0, a1);
    }
    a0 = add2(a0, a1);
    unsigned lo, hi;
    asm("mov.b64 {%0, %1}, %2;" : "=r"(lo), "=r"(hi) : "l"(a0));
    return warp_red(__uint_as_float(lo) + __uint_as_float(hi));
}

// R2 barrier, unchanged.
#define GRID_SYNC() do {                                                      \
    __syncthreads();                                                          \
    if (tid == 0) {                                                           \
        __threadfence();                                                      \
        atomicAdd(&g_bar, 1u);                                                \
        ep++;                                                                 \
        unsigned tgt = ep * (unsigned)NCTA;                                   \
        unsigned v;                                                           \
        while (1) {                                                           \
            asm volatile("ld.global.acquire.gpu.u32 %0, [%1];"                \
                         : "=r"(v) : "l"(&g_bar));                            \
            if (v >= tgt) break;                                              \
            __nanosleep(32);                                                  \
        }                                                                     \
    }                                                                         \
    __syncthreads();                                                          \
} while (0)

__global__ void __launch_bounds__(NTHR, 1) resrnn_seq(
    const float* __restrict__ h0,
    const float* __restrict__ l2b,
    const float* __restrict__ xh2hb)
{
    __shared__ float4 hs4[HD / 4];   //  8 KB: h_prev, swizzled
    __shared__ float4 sb4[H2 / 4];   // 16 KB: phase input vector, swizzled
    const int tid  = threadIdx.x;
    const int wid  = tid >> 5;
    const int lane = tid & 31;
    const int bid  = blockIdx.x;
    const int r    = bid + NCTA * wid;   // this warp's output row
    unsigned  ep   = 0;

    const uint4* qA = reinterpret_cast<const uint4*>(
        g_qL1h + (size_t)(r < H2 ? r : 0) * HD);
    const uint4* qB = reinterpret_cast<const uint4*>(
        g_qL2 + (size_t)(r < H2 ? r : 0) * H2);
    const uint4* qC = reinterpret_cast<const uint4*>(
        g_qXh + (size_t)(r < HD ? r : 0) * H2);

    // initial prefetch: phase A of step 0
    uint4 pf0 = {0,0,0,0}, pf1 = {0,0,0,0};
    if (r < H2) { pf0 = __ldcg(qA + lane); pf1 = __ldcg(qA + lane + 32); }

    for (int t = 0; t < T_; t++) {
        const float4* hprev4 = (t == 0)
            ? reinterpret_cast<const float4*>(h0)
            : reinterpret_cast<const float4*>(&g_Hs[(size_t)(t - 1) * HD]);

        // ---- stage h_prev (swizzled); weight prefetch already in flight ----
        for (int j = tid; j < HD / 4; j += NTHR)
            hs4[j ^ ((j >> 3) & 7)] = __ldcg(hprev4 + j);
        __syncthreads();

        // ---- Phase A: z = relu(A1[t] + l1h @ h) ----
        if (r < H2) {
            float s = dotq2<HD / 8>(qA, hs4, lane, pf0, pf1);
            if (lane == 0) {
                float zz = __ldcg(&g_A1[(size_t)t * H2 + r]) + g_sL1h[r] * s;
                g_z[r] = fmaxf(zz, 0.f);
            }
        }
        // prefetch phase-B weights across the barrier
        if (r < H2) { pf0 = __ldcg(qB + lane); pf1 = __ldcg(qB + lane + 32); }
        GRID_SYNC();

        // ---- Phase B: y2 = l2 @ z + l2_b ----
        {
            const float4* z4 = reinterpret_cast<const float4*>(g_z);
            for (int j = tid; j < H2 / 4; j += NTHR)
                sb4[j ^ ((j >> 3) & 7)] = __ldcg(z4 + j);
        }
        __syncthreads();
        if (r < H2) {
            float s = dotq2<H2 / 8>(qB, sb4, lane, pf0, pf1);
            if (lane == 0) g_y2[r] = g_sL2[r] * s + __ldcg(l2b + r);
        }
        // prefetch phase-C weights across the barrier
        if (r < HD) { pf0 = __ldcg(qC + lane); pf1 = __ldcg(qC + lane + 32); }
        GRID_SYNC();

        // ---- Phase C: temp = relu(xh + y2); h' = xh2h @ temp + b ----
        {
            const float4* xi4 = reinterpret_cast<const float4*>(
                &g_XI[(size_t)t * HD]);
            const float4* y4 = reinterpret_cast<const float4*>(g_y2);
            for (int j = tid; j < H2 / 4; j += NTHR) {
                float4 xh;
                if (j < HD / 4) {
                    xh = __ldcg(xi4 + j);
                } else {
                    int jj = j - HD / 4;
                    xh = hs4[jj ^ ((jj >> 3) & 7)];   // unswizzle h
                }
                float4 y = __ldcg(y4 + j);
                float4 tv;
                tv.x = fmaxf(xh.x + y.x, 0.f);
                tv.y = fmaxf(xh.y + y.y, 0.f);
                tv.z = fmaxf(xh.z + y.z, 0.f);
                tv.w = fmaxf(xh.w + y.w, 0.f);
                sb4[j ^ ((j >> 3) & 7)] = tv;
            }
        }
        __syncthreads();
        if (r < HD) {
            float s = dotq2<H2 / 8>(qC, sb4, lane, pf0, pf1);
            if (lane == 0)
                g_Hs[(size_t)t * HD + r] = g_sXh[r] * s + __ldcg(xh2hb + r);
        }
        // prefetch next step's phase-A weights across the barrier
        if (r < H2) { pf0 = __ldcg(qA + lane); pf1 = __ldcg(qA + lane + 32); }
        GRID_SYNC();
    }

    // Reset barrier for next graph replay (handshake: nobody still spinning).
    if (tid == 0) {
        __threadfence();
        atomicAdd(&g_done, 1u);
        if (bid == 0) {
            unsigned v;
            while (1) {
                asm volatile("ld.global.acquire.gpu.u32 %0, [%1];"
                             : "=r"(v) : "l"(&g_done));
                if (v >= (unsigned)NCTA) break;
                __nanosleep(64);
            }
            g_bar  = 0u;
            g_done = 0u;
            __threadfence();
        }
    }
}

__global__ void copy_hfinal(float* __restrict__ out)
{
    int i = blockIdx.x * blockDim.x + threadIdx.x;
    if (i < HD) out[i] = g_Hs[(size_t)(T_ - 1) * HD + i];
}

// ---------------------------------------------------------------------------
extern "C" void kernel_launch(void* const* d_in, const int* in_sizes, int n_in,
                              void* d_out, int out_size)
{
    const float* x      = (const float*)d_in[0];
    const float* h0     = (const float*)d_in[1];
    const float* inp_w  = (const float*)d_in[2];
    const float* inp_b  = (const float*)d_in[3];
    const float* l1_w   = (const float*)d_in[4];
    const float* l1_b   = (const float*)d_in[5];
    const float* l2_w   = (const float*)d_in[6];
    const float* l2_b   = (const float*)d_in[7];
    const float* xh2h_w = (const float*)d_in[8];
    const float* xh2h_b = (const float*)d_in[9];
    const float* out_w  = (const float*)d_in[10];
    const float* out_b  = (const float*)d_in[11];

    float *pXI, *pA1, *pHs, *pSL1h, *pSL2, *pSXh;
    unsigned short *pQL1h, *pQL2, *pQXh;
    cudaGetSymbolAddress((void**)&pXI,   g_XI);
    cudaGetSymbolAddress((void**)&pA1,   g_A1);
    cudaGetSymbolAddress((void**)&pHs,   g_Hs);
    cudaGetSymbolAddress((void**)&pQL1h, g_qL1h);
    cudaGetSymbolAddress((void**)&pQL2,  g_qL2);
    cudaGetSymbolAddress((void**)&pQXh,  g_qXh);
    cudaGetSymbolAddress((void**)&pSL1h, g_sL1h);
    cudaGetSymbolAddress((void**)&pSL2,  g_sL2);
    cudaGetSymbolAddress((void**)&pSXh,  g_sXh);

    // Quantize recurrent weights (int16 + per-row scale)
    quantize_rows<<<H2, 256>>>(l1_w,   H2, HD, HD, pQL1h, pSL1h);
    quantize_rows<<<H2, 256>>>(l2_w,   H2, 0,  H2, pQL2,  pSL2);
    quantize_rows<<<HD, 256>>>(xh2h_w, H2, 0,  H2, pQXh,  pSXh);

    // K1: XI[512,2048] = x * inp_w^T + inp_b
    gemm_tt<<<dim3(HD / 64, T_ / 64), 256>>>(x, IND, inp_w, IND, inp_b,
                                             pXI, HD, IND);
    // K2: A1[512,4096] = XI * l1_w[:, :2048]^T + l1_b
    gemm_tt<<<dim3(H2 / 64, T_ / 64), 256>>>(pXI, HD, l1_w, H2, l1_b,
                                             pA1, H2, HD);
    // Sequential recurrence
    resrnn_seq<<<NCTA, NTHR>>>(h0, l2_b, xh2h_b);

    // K3: ys[512,1024] = Hs * out_w^T + out_b
    gemm_tt<<<dim3(OUTD / 64, T_ / 64), 256>>>(pHs, HD, out_w, HD, out_b,
                                               (float*)d_out, OUTD, HD);

    if (out_size >= T_ * OUTD + HD) {
        copy_hfinal<<<2, NTHR>>>((float*)d_out + (size_t)T_ * OUTD);
    }
}